// round 15
// baseline (speedup 1.0000x reference)
#include <cuda_runtime.h>
#include <cuda_fp16.h>
#include <math.h>
#include <stdint.h>

#define BB 64
#define CC 1024
#define TT 512
#define CBOT 256
#define GG 8
#define CPG 128
#define GN_EPS 1e-5f

#define TB 128
#define BK 32
#define A_STAGE 8192
#define B_STAGE 8192
#define HS_BYTES 65536
#define SMEM_MEGA (HS_BYTES + 3 * (A_STAGE + B_STAGE))   // 114688

// ---- scratch (__device__ globals: allocation-free rule) ----
__device__ __align__(256) __half g_x16[(size_t)BB * CC * TT];   // groupnorm(x) fp16
__device__ __align__(256) __half g_wd16[CBOT * CC];
__device__ __align__(256) __half g_wu16[CC * CBOT];

// ---------------------------------------------------------------- helpers ----
__device__ __forceinline__ uint32_t smem_u32(const void* p) {
    return (uint32_t)__cvta_generic_to_shared(p);
}
__device__ __forceinline__ void cp_async16(uint32_t s, const void* g) {
    asm volatile("cp.async.cg.shared.global [%0], [%1], 16;" :: "r"(s), "l"(g));
}
#define CP_COMMIT()  asm volatile("cp.async.commit_group;")
#define CP_WAIT(n)   asm volatile("cp.async.wait_group %0;" :: "n"(n))

__device__ __forceinline__ uint32_t a_addr(uint32_t base, int m, int c) {
    int slot = (((m & 1) << 2) | c) ^ ((m >> 1) & 7);
    return base + (m >> 1) * 128 + slot * 16;
}
__device__ __forceinline__ uint32_t b_addr(uint32_t base, int k, int nc) {
    int slot = nc ^ (k & 7);
    return base + k * 256 + slot * 16;
}

__device__ __forceinline__ void ldsm_x4(uint32_t* r, uint32_t addr) {
    asm volatile("ldmatrix.sync.aligned.m8n8.x4.shared.b16 {%0,%1,%2,%3}, [%4];"
                 : "=r"(r[0]), "=r"(r[1]), "=r"(r[2]), "=r"(r[3]) : "r"(addr));
}
__device__ __forceinline__ void ldsm_x4_t(uint32_t* r, uint32_t addr) {
    asm volatile("ldmatrix.sync.aligned.m8n8.x4.trans.shared.b16 {%0,%1,%2,%3}, [%4];"
                 : "=r"(r[0]), "=r"(r[1]), "=r"(r[2]), "=r"(r[3]) : "r"(addr));
}
__device__ __forceinline__ void mma16816(float* c, const uint32_t* a, const uint32_t* b) {
    asm volatile(
        "mma.sync.aligned.m16n8k16.row.col.f32.f16.f16.f32 "
        "{%0,%1,%2,%3}, {%4,%5,%6,%7}, {%8,%9}, {%0,%1,%2,%3};"
        : "+f"(c[0]), "+f"(c[1]), "+f"(c[2]), "+f"(c[3])
        : "r"(a[0]), "r"(a[1]), "r"(a[2]), "r"(a[3]), "r"(b[0]), "r"(b[1]));
}
__device__ __forceinline__ float mishf(float v) {
    if (v > 15.f) return v;
    float e = __expf(v);
    float w = (1.f + e) * (1.f + e);
    return v * (w - 1.f) / (w + 1.f);
}

// f32-accumulate compute (R11-proven)
__device__ __forceinline__ void compute_k32(float acc[4][4][4], uint32_t ca,
                                            uint32_t cbBase, int kbase,
                                            int warp_m, int warp_n,
                                            int lm_m, int lm_c) {
#pragma unroll
    for (int ks = 0; ks < 2; ++ks) {
        uint32_t a[4][4], bf[2][4];
#pragma unroll
        for (int i = 0; i < 4; i++)
            ldsm_x4(a[i], a_addr(ca, warp_m * 64 + i * 16 + lm_m, ks * 2 + lm_c));
#pragma unroll
        for (int p = 0; p < 2; p++)
            ldsm_x4_t(bf[p], b_addr(cbBase, kbase + ks * 16 + lm_m,
                                    warp_n * 4 + p * 2 + lm_c));
#pragma unroll
        for (int i = 0; i < 4; i++)
#pragma unroll
            for (int j = 0; j < 4; j++)
                mma16816(acc[i][j], a[i], &bf[j >> 1][(j & 1) * 2]);
    }
}

// --- GroupNorm single-pass: register stash, stats, affine, fp16 write -------
__global__ __launch_bounds__(1024)
void gn_norm_kernel(const float* __restrict__ x,
                    const float* __restrict__ gamma,
                    const float* __restrict__ beta,
                    const float* __restrict__ wd,
                    const float* __restrict__ wu) {
    __shared__ float ws[32], wss[32], s_sc[CPG], s_sh[CPG];
    int b = blockIdx.x >> 3, g = blockIdx.x & 7;

    if (threadIdx.x < 512) {
        int i = blockIdx.x * 512 + threadIdx.x;
        g_wd16[i] = __float2half_rn(wd[i]);
        g_wu16[i] = __float2half_rn(wu[i]);
    }

    const size_t base = ((size_t)b * CC + (size_t)g * CPG) * TT;
    const float4* xp = (const float4*)(x + base);
    uint2* op = (uint2*)(g_x16 + base);

    uint2 stash[16];
    float s = 0.f, ss = 0.f;
#pragma unroll
    for (int i = 0; i < 16; i++) {
        int idx = i * 1024 + threadIdx.x;
        float4 v = xp[idx];
        s  += v.x + v.y + v.z + v.w;
        ss += v.x*v.x + v.y*v.y + v.z*v.z + v.w*v.w;
        __half2 h0 = __floats2half2_rn(v.x, v.y);
        __half2 h1 = __floats2half2_rn(v.z, v.w);
        stash[i].x = *(uint32_t*)&h0;
        stash[i].y = *(uint32_t*)&h1;
    }
#pragma unroll
    for (int o = 16; o; o >>= 1) {
        s  += __shfl_xor_sync(0xffffffffu, s, o);
        ss += __shfl_xor_sync(0xffffffffu, ss, o);
    }
    int w = threadIdx.x >> 5, l = threadIdx.x & 31;
    if (l == 0) { ws[w] = s; wss[w] = ss; }
    __syncthreads();
    if (threadIdx.x < CPG) {
        float S = 0.f, SS = 0.f;
#pragma unroll
        for (int i = 0; i < 32; i++) { S += ws[i]; SS += wss[i]; }
        float mean = S / 65536.f;
        float var  = SS / 65536.f - mean * mean;
        float rstd = rsqrtf(var + GN_EPS);
        int c = g * CPG + threadIdx.x;
        float sc = rstd * gamma[c];
        s_sc[threadIdx.x] = sc;
        s_sh[threadIdx.x] = beta[c] - mean * sc;
    }
    __syncthreads();

#pragma unroll
    for (int i = 0; i < 16; i++) {
        int idx = i * 1024 + threadIdx.x;
        int c = idx >> 7;
        float sc = s_sc[c], sh = s_sh[c];
        float2 f0 = __half22float2(*(__half2*)&stash[i].x);
        float2 f1 = __half22float2(*(__half2*)&stash[i].y);
        __half2 o0 = __floats2half2_rn(fmaf(f0.x, sc, sh), fmaf(f0.y, sc, sh));
        __half2 o1 = __floats2half2_rn(fmaf(f1.x, sc, sh), fmaf(f1.y, sc, sh));
        uint2 pk;
        pk.x = *(uint32_t*)&o0;
        pk.y = *(uint32_t*)&o1;
        op[idx] = pk;
    }
}

// ------------------------------- fused down+up megakernel -------------------
// Phase 1: single 64-iter pipeline (both m-halves, epilogue inline).
// Tail slots j=64,65 pre-load phase-2 A stages 4,5. Phase 2 stage map (v+4)%6.
__global__ __launch_bounds__(256, 2)
void mega_kernel(const float* __restrict__ xres,
                 const float* __restrict__ b_down,
                 const float* __restrict__ b_up,
                 float* __restrict__ outp) {
    extern __shared__ __align__(1024) char smem_raw[];
    const uint32_t hS = smem_u32(smem_raw);
    const uint32_t sA = hS + HS_BYTES;
    const uint32_t sB = sA + 3 * A_STAGE;

    const int tid  = threadIdx.x;
    const int lane = tid & 31;
    const int wid  = tid >> 5;
    const int warp_m = wid >> 2;
    const int warp_n = wid & 3;
    const int grp = lane >> 2;
    const int lin = lane & 3;
    const int lm_m = (lane & 7) + ((lane >> 3) & 1) * 8;
    const int lm_c = lane >> 4;

    const int tb = blockIdx.x;
    const int b  = blockIdx.y;
    const int t0 = tb * TB;

    const int aw_m = tid >> 1;
    const int aw_c = (tid & 1) * 2;
    const int bw_k = tid >> 3;
    const int bw_nc = (tid & 7) * 2;

    float acc[4][4][4];
#pragma unroll
    for (int i = 0; i < 4; i++)
#pragma unroll
        for (int j = 0; j < 4; j++)
#pragma unroll
            for (int r = 0; r < 4; r++) acc[i][j][r] = 0.f;

    // ======================= PHASE 1: h tile in smem =======================
    const __half* Bb = g_x16 + (size_t)b * CC * TT + t0;

    // prologue: stages 0,1 (j=0,1; m-half 0)
#pragma unroll
    for (int sst = 0; sst < 2; ++sst) {
        const int k0 = sst * BK;
        const uint32_t da = sA + sst * A_STAGE;
        const uint32_t db = sB + sst * B_STAGE;
        cp_async16(a_addr(da, aw_m, aw_c),     g_wd16 + (size_t)aw_m * CC + k0 + aw_c * 8);
        cp_async16(a_addr(da, aw_m, aw_c + 1), g_wd16 + (size_t)aw_m * CC + k0 + aw_c * 8 + 8);
        cp_async16(b_addr(db, bw_k, bw_nc),     Bb + (size_t)(k0 + bw_k) * TT + bw_nc * 8);
        cp_async16(b_addr(db, bw_k, bw_nc + 1), Bb + (size_t)(k0 + bw_k) * TT + bw_nc * 8 + 8);
        CP_COMMIT();
    }
    CP_WAIT(1);
    __syncthreads();

    for (int it = 0; it < 64; ++it) {
        const int j = it + 2;
        if (j < 64) {
            const int st = j % 3;
            const int k0 = (j & 31) * BK;
            const __half* Ab = g_wd16 + (size_t)(j >> 5) * 128 * CC;
            const uint32_t da = sA + st * A_STAGE;
            const uint32_t db = sB + st * B_STAGE;
            cp_async16(a_addr(da, aw_m, aw_c),     Ab + (size_t)aw_m * CC + k0 + aw_c * 8);
            cp_async16(a_addr(da, aw_m, aw_c + 1), Ab + (size_t)aw_m * CC + k0 + aw_c * 8 + 8);
            cp_async16(b_addr(db, bw_k, bw_nc),     Bb + (size_t)(k0 + bw_k) * TT + bw_nc * 8);
            cp_async16(b_addr(db, bw_k, bw_nc + 1), Bb + (size_t)(k0 + bw_k) * TT + bw_nc * 8 + 8);
        } else if (j == 64) {
            // pre-load phase-2 stage 4 (sB+8K = B stage 1; free since it=61)
            const uint32_t da = sA + 4 * A_STAGE;
            cp_async16(a_addr(da, aw_m, aw_c),     g_wu16 + (size_t)aw_m * CBOT + aw_c * 8);
            cp_async16(a_addr(da, aw_m, aw_c + 1), g_wu16 + (size_t)aw_m * CBOT + aw_c * 8 + 8);
        } else {  // j == 65
            // pre-load phase-2 stage 5 (sB+16K = B stage 2; free since it=62)
            const uint32_t da = sA + 5 * A_STAGE;
            cp_async16(a_addr(da, aw_m, aw_c),     g_wu16 + (size_t)aw_m * CBOT + BK + aw_c * 8);
            cp_async16(a_addr(da, aw_m, aw_c + 1), g_wu16 + (size_t)aw_m * CBOT + BK + aw_c * 8 + 8);
        }
        CP_COMMIT();

        const int cs = it % 3;
        compute_k32(acc, sA + cs * A_STAGE, sB + cs * B_STAGE, 0,
                    warp_m, warp_n, lm_m, lm_c);

        if ((it & 31) == 31) {
            // epilogue for m-half hh: bias + mish -> hS, reset acc
            const int hh = it >> 5;
#pragma unroll
            for (int i = 0; i < 4; i++) {
                const int r0 = hh * 128 + warp_m * 64 + i * 16 + grp;
                const float bv0 = b_down[r0], bv1 = b_down[r0 + 8];
#pragma unroll
                for (int j2 = 0; j2 < 4; j2++) {
                    const int c = warp_n * 32 + j2 * 8 + 2 * lin;
                    const int nc = c >> 3, off = (c & 7) * 2;
                    __half2 v0 = __floats2half2_rn(mishf(acc[i][j2][0] + bv0),
                                                   mishf(acc[i][j2][1] + bv0));
                    __half2 v1 = __floats2half2_rn(mishf(acc[i][j2][2] + bv1),
                                                   mishf(acc[i][j2][3] + bv1));
                    uint32_t ad0 = b_addr(hS, r0, nc) + off;
                    uint32_t ad1 = b_addr(hS, r0 + 8, nc) + off;
                    asm volatile("st.shared.b32 [%0], %1;" :: "r"(ad0), "r"(*(uint32_t*)&v0));
                    asm volatile("st.shared.b32 [%0], %1;" :: "r"(ad1), "r"(*(uint32_t*)&v1));
                }
            }
#pragma unroll
            for (int i = 0; i < 4; i++)
#pragma unroll
                for (int j2 = 0; j2 < 4; j2++)
#pragma unroll
                    for (int r = 0; r < 4; r++) acc[i][j2][r] = 0.f;
        }

        CP_WAIT(1);
        __syncthreads();
    }

    // ======================= PHASE 2: out = w_up @ hS ====================
    // Stage map s(v) = (v+4)%6. Stages 4,5 pre-loaded in phase-1 tail.
    // Post-loop: issue stages 0,1 (regions = phase-1 A stages 0,1, dead).
#pragma unroll
    for (int p = 0; p < 2; ++p) {
        const uint32_t da = sA + p * A_STAGE;
        const int k0 = (p + 2) * BK;           // v = p+2 -> mt 0, k0 = 64, 96
        cp_async16(a_addr(da, aw_m, aw_c),     g_wu16 + (size_t)aw_m * CBOT + k0 + aw_c * 8);
        cp_async16(a_addr(da, aw_m, aw_c + 1), g_wu16 + (size_t)aw_m * CBOT + k0 + aw_c * 8 + 8);
        CP_COMMIT();
    }

    const int NV = 64;
    for (int vit = 0; vit < NV; vit += 2) {
        CP_WAIT(2);
        __syncthreads();

#pragma unroll
        for (int q = 4; q <= 5; ++q) {
            const int j = vit + q;
            if (j < NV) {
                const uint32_t da = sA + ((j + 4) % 6) * A_STAGE;
                const int k0 = (j & 7) * BK;
                const __half* Ab2 = g_wu16 + (size_t)(j >> 3) * 128 * CBOT;
                cp_async16(a_addr(da, aw_m, aw_c),     Ab2 + (size_t)aw_m * CBOT + k0 + aw_c * 8);
                cp_async16(a_addr(da, aw_m, aw_c + 1), Ab2 + (size_t)aw_m * CBOT + k0 + aw_c * 8 + 8);
            }
            CP_COMMIT();
        }

#pragma unroll
        for (int u = 0; u < 2; ++u) {
            const int v = vit + u;
            compute_k32(acc, sA + ((v + 4) % 6) * A_STAGE, hS, (v & 7) * BK,
                        warp_m, warp_n, lm_m, lm_c);

            if ((v & 7) == 7) {
                const int mt = v >> 3;
#pragma unroll
                for (int i = 0; i < 4; i++) {
                    const int row = mt * 128 + warp_m * 64 + i * 16 + grp;
                    const float bv0 = b_up[row], bv1 = b_up[row + 8];
                    const size_t base0 = ((size_t)b * CC + row) * TT + t0;
#pragma unroll
                    for (int j2 = 0; j2 < 4; j2++) {
                        const int c = warp_n * 32 + j2 * 8 + 2 * lin;
                        const size_t o0 = base0 + c;
                        const size_t o1 = o0 + (size_t)8 * TT;
                        float2 ra = *(const float2*)(xres + o0);
                        float2 rb = *(const float2*)(xres + o1);
                        *(float2*)(outp + o0) = make_float2(acc[i][j2][0] + bv0 + ra.x,
                                                            acc[i][j2][1] + bv0 + ra.y);
                        *(float2*)(outp + o1) = make_float2(acc[i][j2][2] + bv1 + rb.x,
                                                            acc[i][j2][3] + bv1 + rb.y);
                    }
                }
#pragma unroll
                for (int i = 0; i < 4; i++)
#pragma unroll
                    for (int j2 = 0; j2 < 4; j2++)
#pragma unroll
                        for (int r = 0; r < 4; r++) acc[i][j2][r] = 0.f;
            }
        }
    }
}

// ---------------------------------------------------------------- launch ----
extern "C" void kernel_launch(void* const* d_in, const int* in_sizes, int n_in,
                              void* d_out, int out_size) {
    const float* x      = (const float*)d_in[0];
    const float* gamma  = (const float*)d_in[1];
    const float* beta   = (const float*)d_in[2];
    const float* w_down = (const float*)d_in[3];
    const float* b_down = (const float*)d_in[4];
    const float* w_up   = (const float*)d_in[5];
    const float* b_up   = (const float*)d_in[6];
    float* out = (float*)d_out;

    cudaFuncSetAttribute(mega_kernel,
                         cudaFuncAttributeMaxDynamicSharedMemorySize, SMEM_MEGA);

    gn_norm_kernel<<<BB * GG, 1024>>>(x, gamma, beta, w_down, w_up);
    mega_kernel<<<dim3(TT / TB, BB), 256, SMEM_MEGA>>>(x, b_down, b_up, out);
}

// round 16
// speedup vs baseline: 1.0294x; 1.0294x over previous
#include <cuda_runtime.h>
#include <cuda_fp16.h>
#include <math.h>
#include <stdint.h>

#define BB 64
#define CC 1024
#define TT 512
#define CBOT 256
#define GG 8
#define CPG 128
#define GN_EPS 1e-5f

#define TB 128
#define BK 32
#define A_STAGE 8192
#define B_STAGE 8192
#define HS_BYTES 65536
#define SMEM_MEGA (HS_BYTES + 3 * (A_STAGE + B_STAGE))   // 114688

// ---- scratch (__device__ globals: allocation-free rule) ----
__device__ __align__(256) __half g_x16[(size_t)BB * CC * TT];   // groupnorm(x) fp16
__device__ __align__(256) __half g_wd16[CBOT * CC];
__device__ __align__(256) __half g_wu16[CC * CBOT];

// ---------------------------------------------------------------- helpers ----
__device__ __forceinline__ uint32_t smem_u32(const void* p) {
    return (uint32_t)__cvta_generic_to_shared(p);
}
__device__ __forceinline__ void cp_async16(uint32_t s, const void* g) {
    asm volatile("cp.async.cg.shared.global [%0], [%1], 16;" :: "r"(s), "l"(g));
}
#define CP_COMMIT()  asm volatile("cp.async.commit_group;")
#define CP_WAIT(n)   asm volatile("cp.async.wait_group %0;" :: "n"(n))

__device__ __forceinline__ uint32_t a_addr(uint32_t base, int m, int c) {
    int slot = (((m & 1) << 2) | c) ^ ((m >> 1) & 7);
    return base + (m >> 1) * 128 + slot * 16;
}
__device__ __forceinline__ uint32_t b_addr(uint32_t base, int k, int nc) {
    int slot = nc ^ (k & 7);
    return base + k * 256 + slot * 16;
}

__device__ __forceinline__ void ldsm_x4(uint32_t* r, uint32_t addr) {
    asm volatile("ldmatrix.sync.aligned.m8n8.x4.shared.b16 {%0,%1,%2,%3}, [%4];"
                 : "=r"(r[0]), "=r"(r[1]), "=r"(r[2]), "=r"(r[3]) : "r"(addr));
}
__device__ __forceinline__ void ldsm_x4_t(uint32_t* r, uint32_t addr) {
    asm volatile("ldmatrix.sync.aligned.m8n8.x4.trans.shared.b16 {%0,%1,%2,%3}, [%4];"
                 : "=r"(r[0]), "=r"(r[1]), "=r"(r[2]), "=r"(r[3]) : "r"(addr));
}
__device__ __forceinline__ void mma16816(float* c, const uint32_t* a, const uint32_t* b) {
    asm volatile(
        "mma.sync.aligned.m16n8k16.row.col.f32.f16.f16.f32 "
        "{%0,%1,%2,%3}, {%4,%5,%6,%7}, {%8,%9}, {%0,%1,%2,%3};"
        : "+f"(c[0]), "+f"(c[1]), "+f"(c[2]), "+f"(c[3])
        : "r"(a[0]), "r"(a[1]), "r"(a[2]), "r"(a[3]), "r"(b[0]), "r"(b[1]));
}
__device__ __forceinline__ float mishf(float v) {
    if (v > 15.f) return v;
    float e = __expf(v);
    float w = (1.f + e) * (1.f + e);
    return v * (w - 1.f) / (w + 1.f);
}

// f32-acc compute, full fragment prefetch: all 12 ldmatrix issued before the
// 32 HMMAs. Per-acc MMA order (ks0 then ks1) preserved -> bitwise identical.
__device__ __forceinline__ void compute_k32(float acc[4][4][4], uint32_t ca,
                                            uint32_t cbBase, int kbase,
                                            int warp_m, int warp_n,
                                            int lm_m, int lm_c) {
    uint32_t a[2][4][4], bf[2][2][4];
#pragma unroll
    for (int ks = 0; ks < 2; ++ks) {
#pragma unroll
        for (int i = 0; i < 4; i++)
            ldsm_x4(a[ks][i], a_addr(ca, warp_m * 64 + i * 16 + lm_m, ks * 2 + lm_c));
#pragma unroll
        for (int p = 0; p < 2; p++)
            ldsm_x4_t(bf[ks][p], b_addr(cbBase, kbase + ks * 16 + lm_m,
                                        warp_n * 4 + p * 2 + lm_c));
    }
#pragma unroll
    for (int ks = 0; ks < 2; ++ks)
#pragma unroll
        for (int i = 0; i < 4; i++)
#pragma unroll
            for (int j = 0; j < 4; j++)
                mma16816(acc[i][j], a[ks][i], &bf[ks][j >> 1][(j & 1) * 2]);
}

// --- GroupNorm single-pass: register stash, stats, affine, fp16 write -------
__global__ __launch_bounds__(1024)
void gn_norm_kernel(const float* __restrict__ x,
                    const float* __restrict__ gamma,
                    const float* __restrict__ beta,
                    const float* __restrict__ wd,
                    const float* __restrict__ wu) {
    __shared__ float ws[32], wss[32], s_sc[CPG], s_sh[CPG];
    int b = blockIdx.x >> 3, g = blockIdx.x & 7;

    if (threadIdx.x < 512) {
        int i = blockIdx.x * 512 + threadIdx.x;
        g_wd16[i] = __float2half_rn(wd[i]);
        g_wu16[i] = __float2half_rn(wu[i]);
    }

    const size_t base = ((size_t)b * CC + (size_t)g * CPG) * TT;
    const float4* xp = (const float4*)(x + base);
    uint2* op = (uint2*)(g_x16 + base);

    uint2 stash[16];
    float s = 0.f, ss = 0.f;
#pragma unroll
    for (int i = 0; i < 16; i++) {
        int idx = i * 1024 + threadIdx.x;
        float4 v = xp[idx];
        s  += v.x + v.y + v.z + v.w;
        ss += v.x*v.x + v.y*v.y + v.z*v.z + v.w*v.w;
        __half2 h0 = __floats2half2_rn(v.x, v.y);
        __half2 h1 = __floats2half2_rn(v.z, v.w);
        stash[i].x = *(uint32_t*)&h0;
        stash[i].y = *(uint32_t*)&h1;
    }
#pragma unroll
    for (int o = 16; o; o >>= 1) {
        s  += __shfl_xor_sync(0xffffffffu, s, o);
        ss += __shfl_xor_sync(0xffffffffu, ss, o);
    }
    int w = threadIdx.x >> 5, l = threadIdx.x & 31;
    if (l == 0) { ws[w] = s; wss[w] = ss; }
    __syncthreads();
    if (threadIdx.x < CPG) {
        float S = 0.f, SS = 0.f;
#pragma unroll
        for (int i = 0; i < 32; i++) { S += ws[i]; SS += wss[i]; }
        float mean = S / 65536.f;
        float var  = SS / 65536.f - mean * mean;
        float rstd = rsqrtf(var + GN_EPS);
        int c = g * CPG + threadIdx.x;
        float sc = rstd * gamma[c];
        s_sc[threadIdx.x] = sc;
        s_sh[threadIdx.x] = beta[c] - mean * sc;
    }
    __syncthreads();

#pragma unroll
    for (int i = 0; i < 16; i++) {
        int idx = i * 1024 + threadIdx.x;
        int c = idx >> 7;
        float sc = s_sc[c], sh = s_sh[c];
        float2 f0 = __half22float2(*(__half2*)&stash[i].x);
        float2 f1 = __half22float2(*(__half2*)&stash[i].y);
        __half2 o0 = __floats2half2_rn(fmaf(f0.x, sc, sh), fmaf(f0.y, sc, sh));
        __half2 o1 = __floats2half2_rn(fmaf(f1.x, sc, sh), fmaf(f1.y, sc, sh));
        uint2 pk;
        pk.x = *(uint32_t*)&o0;
        pk.y = *(uint32_t*)&o1;
        op[idx] = pk;
    }
}

// ------------------------------- fused down+up megakernel (R14) -------------
__global__ __launch_bounds__(256, 2)
void mega_kernel(const float* __restrict__ xres,
                 const float* __restrict__ b_down,
                 const float* __restrict__ b_up,
                 float* __restrict__ outp) {
    extern __shared__ __align__(1024) char smem_raw[];
    const uint32_t hS = smem_u32(smem_raw);
    const uint32_t sA = hS + HS_BYTES;
    const uint32_t sB = sA + 3 * A_STAGE;

    const int tid  = threadIdx.x;
    const int lane = tid & 31;
    const int wid  = tid >> 5;
    const int warp_m = wid >> 2;
    const int warp_n = wid & 3;
    const int grp = lane >> 2;
    const int lin = lane & 3;
    const int lm_m = (lane & 7) + ((lane >> 3) & 1) * 8;
    const int lm_c = lane >> 4;

    const int tb = blockIdx.x;
    const int b  = blockIdx.y;
    const int t0 = tb * TB;

    const int aw_m = tid >> 1;
    const int aw_c = (tid & 1) * 2;
    const int bw_k = tid >> 3;
    const int bw_nc = (tid & 7) * 2;

    float acc[4][4][4];

    // ======================= PHASE 1: h tile in smem =======================
    const __half* Bb = g_x16 + (size_t)b * CC * TT + t0;

#pragma unroll 1
    for (int hh = 0; hh < 2; ++hh) {
        const __half* Ab = g_wd16 + (size_t)hh * 128 * CC;
#pragma unroll
        for (int i = 0; i < 4; i++)
#pragma unroll
            for (int j = 0; j < 4; j++)
#pragma unroll
                for (int r = 0; r < 4; r++) acc[i][j][r] = 0.f;

#pragma unroll
        for (int sst = 0; sst < 2; ++sst) {
            const int k0 = sst * BK;
            const uint32_t da = sA + sst * A_STAGE;
            const uint32_t db = sB + sst * B_STAGE;
            cp_async16(a_addr(da, aw_m, aw_c),     Ab + (size_t)aw_m * CC + k0 + aw_c * 8);
            cp_async16(a_addr(da, aw_m, aw_c + 1), Ab + (size_t)aw_m * CC + k0 + aw_c * 8 + 8);
            cp_async16(b_addr(db, bw_k, bw_nc),     Bb + (size_t)(k0 + bw_k) * TT + bw_nc * 8);
            cp_async16(b_addr(db, bw_k, bw_nc + 1), Bb + (size_t)(k0 + bw_k) * TT + bw_nc * 8 + 8);
            CP_COMMIT();
        }
        CP_WAIT(1);
        __syncthreads();

        const int NIT = CC / BK;   // 32
        for (int it = 0; it < NIT; ++it) {
            const int j = it + 2;
            if (j < NIT) {
                const int st = j % 3;
                const int k0 = j * BK;
                const uint32_t da = sA + st * A_STAGE;
                const uint32_t db = sB + st * B_STAGE;
                cp_async16(a_addr(da, aw_m, aw_c),     Ab + (size_t)aw_m * CC + k0 + aw_c * 8);
                cp_async16(a_addr(da, aw_m, aw_c + 1), Ab + (size_t)aw_m * CC + k0 + aw_c * 8 + 8);
                cp_async16(b_addr(db, bw_k, bw_nc),     Bb + (size_t)(k0 + bw_k) * TT + bw_nc * 8);
                cp_async16(b_addr(db, bw_k, bw_nc + 1), Bb + (size_t)(k0 + bw_k) * TT + bw_nc * 8 + 8);
            }
            CP_COMMIT();

            const int cs = it % 3;
            compute_k32(acc, sA + cs * A_STAGE, sB + cs * B_STAGE, 0,
                        warp_m, warp_n, lm_m, lm_c);

            CP_WAIT(1);
            __syncthreads();
        }

        // epilogue: bias + mish -> hS
#pragma unroll
        for (int i = 0; i < 4; i++) {
            const int r0 = hh * 128 + warp_m * 64 + i * 16 + grp;
            const float bv0 = b_down[r0], bv1 = b_down[r0 + 8];
#pragma unroll
            for (int j = 0; j < 4; j++) {
                const int c = warp_n * 32 + j * 8 + 2 * lin;
                const int nc = c >> 3, off = (c & 7) * 2;
                __half2 v0 = __floats2half2_rn(mishf(acc[i][j][0] + bv0),
                                               mishf(acc[i][j][1] + bv0));
                __half2 v1 = __floats2half2_rn(mishf(acc[i][j][2] + bv1),
                                               mishf(acc[i][j][3] + bv1));
                uint32_t ad0 = b_addr(hS, r0, nc) + off;
                uint32_t ad1 = b_addr(hS, r0 + 8, nc) + off;
                asm volatile("st.shared.b32 [%0], %1;" :: "r"(ad0), "r"(*(uint32_t*)&v0));
                asm volatile("st.shared.b32 [%0], %1;" :: "r"(ad1), "r"(*(uint32_t*)&v1));
            }
        }
    }

    // ======================= PHASE 2: out = w_up @ hS ====================
#pragma unroll
    for (int p = 0; p < 4; ++p) {
        const uint32_t da = sA + p * A_STAGE;
        const int k0 = (p & 7) * BK;
        cp_async16(a_addr(da, aw_m, aw_c),     g_wu16 + (size_t)aw_m * CBOT + k0 + aw_c * 8);
        cp_async16(a_addr(da, aw_m, aw_c + 1), g_wu16 + (size_t)aw_m * CBOT + k0 + aw_c * 8 + 8);
        CP_COMMIT();
    }

#pragma unroll
    for (int i = 0; i < 4; i++)
#pragma unroll
        for (int j = 0; j < 4; j++)
#pragma unroll
            for (int r = 0; r < 4; r++) acc[i][j][r] = 0.f;

    const int NV = 64;
    for (int vit = 0; vit < NV; vit += 2) {
        CP_WAIT(2);
        __syncthreads();

#pragma unroll
        for (int q = 4; q <= 5; ++q) {
            const int j = vit + q;
            if (j < NV) {
                const uint32_t da = sA + (j % 6) * A_STAGE;
                const int k0 = (j & 7) * BK;
                const __half* Ab2 = g_wu16 + (size_t)(j >> 3) * 128 * CBOT;
                cp_async16(a_addr(da, aw_m, aw_c),     Ab2 + (size_t)aw_m * CBOT + k0 + aw_c * 8);
                cp_async16(a_addr(da, aw_m, aw_c + 1), Ab2 + (size_t)aw_m * CBOT + k0 + aw_c * 8 + 8);
            }
            CP_COMMIT();
        }

#pragma unroll
        for (int u = 0; u < 2; ++u) {
            const int v = vit + u;
            compute_k32(acc, sA + (v % 6) * A_STAGE, hS, (v & 7) * BK,
                        warp_m, warp_n, lm_m, lm_c);

            if ((v & 7) == 7) {
                const int mt = v >> 3;
#pragma unroll
                for (int i = 0; i < 4; i++) {
                    const int row = mt * 128 + warp_m * 64 + i * 16 + grp;
                    const float bv0 = b_up[row], bv1 = b_up[row + 8];
                    const size_t base0 = ((size_t)b * CC + row) * TT + t0;
#pragma unroll
                    for (int j2 = 0; j2 < 4; j2++) {
                        const int c = warp_n * 32 + j2 * 8 + 2 * lin;
                        const size_t o0 = base0 + c;
                        const size_t o1 = o0 + (size_t)8 * TT;
                        float2 ra = *(const float2*)(xres + o0);
                        float2 rb = *(const float2*)(xres + o1);
                        *(float2*)(outp + o0) = make_float2(acc[i][j2][0] + bv0 + ra.x,
                                                            acc[i][j2][1] + bv0 + ra.y);
                        *(float2*)(outp + o1) = make_float2(acc[i][j2][2] + bv1 + rb.x,
                                                            acc[i][j2][3] + bv1 + rb.y);
                    }
                }
#pragma unroll
                for (int i = 0; i < 4; i++)
#pragma unroll
                    for (int j2 = 0; j2 < 4; j2++)
#pragma unroll
                        for (int r = 0; r < 4; r++) acc[i][j2][r] = 0.f;
            }
        }
    }
}

// ---------------------------------------------------------------- launch ----
extern "C" void kernel_launch(void* const* d_in, const int* in_sizes, int n_in,
                              void* d_out, int out_size) {
    const float* x      = (const float*)d_in[0];
    const float* gamma  = (const float*)d_in[1];
    const float* beta   = (const float*)d_in[2];
    const float* w_down = (const float*)d_in[3];
    const float* b_down = (const float*)d_in[4];
    const float* w_up   = (const float*)d_in[5];
    const float* b_up   = (const float*)d_in[6];
    float* out = (float*)d_out;

    cudaFuncSetAttribute(mega_kernel,
                         cudaFuncAttributeMaxDynamicSharedMemorySize, SMEM_MEGA);

    gn_norm_kernel<<<BB * GG, 1024>>>(x, gamma, beta, w_down, w_up);
    mega_kernel<<<dim3(TT / TB, BB), 256, SMEM_MEGA>>>(x, b_down, b_up, out);
}